// round 1
// baseline (speedup 1.0000x reference)
#include <cuda_runtime.h>

// Depthwise 3x3 conv with hard-softmax (one-hot) kernel == spatial shift.
// out[b,c,h,w] = x[b,c,h+dh,w+dw] (zero outside), (dh,dw) from abs-argmax of
// the 9 weight values (first-max wins, matching jnp.argmax).

// Shapes fixed by the problem: B=16, C=64, H=256, W=256 (fp32).
#define H_DIM 256
#define W_DIM 256

__device__ int g_shift[2];  // {dh, dw}

__global__ void argmax_shift_kernel(const float* __restrict__ w) {
    // Single thread: 9 loads, strict > so the FIRST max wins (jnp.argmax tie rule).
    float best = -1.0f;
    int bi = 0;
#pragma unroll
    for (int i = 0; i < 9; ++i) {
        float a = fabsf(w[i]);
        if (a > best) { best = a; bi = i; }
    }
    g_shift[0] = bi / 3 - 1;  // dh
    g_shift[1] = bi % 3 - 1;  // dw
}

__global__ void __launch_bounds__(256)
shift_copy_kernel(const float* __restrict__ x, float* __restrict__ out, int n4) {
    const int dh = g_shift[0];
    const int dw = g_shift[1];

    int v = blockIdx.x * blockDim.x + threadIdx.x;
    if (v >= n4) return;

    // v indexes float4 units. W=256 -> 64 float4 per row; H=256 rows per (b,c).
    const int w4 = v & 63;          // float4 index in row
    const int h  = (v >> 6) & 255;  // row
    const int bc = v >> 14;         // (b*C + c)

    float4 val = make_float4(0.f, 0.f, 0.f, 0.f);

    const int hi = h + dh;
    if ((unsigned)hi < (unsigned)H_DIM) {
        const float* __restrict__ row = x + ((long long)bc * H_DIM + hi) * W_DIM;
        const int w0 = (w4 << 2) + dw;  // shifted start column
        if (dw == 0) {
            // Aligned fast path
            val = __ldg(reinterpret_cast<const float4*>(row) + w4);
        } else {
            // Misaligned by one element: per-lane guarded scalar loads.
            int wa = w0;
            val.x = ((unsigned)wa     < (unsigned)W_DIM) ? __ldg(row + wa)     : 0.f;
            val.y = ((unsigned)(wa+1) < (unsigned)W_DIM) ? __ldg(row + wa + 1) : 0.f;
            val.z = ((unsigned)(wa+2) < (unsigned)W_DIM) ? __ldg(row + wa + 2) : 0.f;
            val.w = ((unsigned)(wa+3) < (unsigned)W_DIM) ? __ldg(row + wa + 3) : 0.f;
        }
    }

    reinterpret_cast<float4*>(out)[v] = val;
}

extern "C" void kernel_launch(void* const* d_in, const int* in_sizes, int n_in,
                              void* d_out, int out_size) {
    const float* x = (const float*)d_in[0];
    const float* w = (const float*)d_in[1];
    float* out = (float*)d_out;

    argmax_shift_kernel<<<1, 1>>>(w);

    const int n4 = out_size >> 2;  // float4 count = 16,777,216
    const int threads = 256;
    const int blocks = (n4 + threads - 1) / threads;
    shift_copy_kernel<<<blocks, threads>>>(x, out, n4);
}